// round 9
// baseline (speedup 1.0000x reference)
#include <cuda_runtime.h>
#include <cuda_bf16.h>
#include <stdint.h>
#include <math.h>

#define B_ 4
#define N_ 4096
#define D_ 256
#define K_ 32
#define NC 40
#define INV_T 14.285714285714285714f

// hi-only bf16 normalized features (K = 256)
__device__ __nv_bfloat16 g_a[(size_t)B_ * N_ * D_];
__device__ __nv_bfloat16 g_b[(size_t)B_ * N_ * D_];
// exact fp32 normalized features
__device__ float g_f1n[(size_t)B_ * N_ * D_];
__device__ float g_f2n[(size_t)B_ * N_ * D_];
// candidate scratch
__device__ float g_cv[(size_t)B_ * N_ * NC];
__device__ int   g_ci[(size_t)B_ * N_ * NC];

// ---------------------------------------------------------------------------
__device__ __forceinline__ uint32_t smem_u32(const void* p) {
    uint32_t a;
    asm("{ .reg .u64 t; cvta.to.shared.u64 t, %1; cvt.u32.u64 %0, t; }" : "=r"(a) : "l"(p));
    return a;
}
__device__ __forceinline__ void cp16(uint32_t dst, const void* src) {
    asm volatile("cp.async.cg.shared.global [%0], [%1], 16;" :: "r"(dst), "l"(src));
}
#define CP_COMMIT() asm volatile("cp.async.commit_group;" ::: "memory")
#define CP_WAIT1()  asm volatile("cp.async.wait_group 1;" ::: "memory")

__device__ __forceinline__ uint32_t swz(uint32_t x) { return x ^ ((x >> 3) & 0x70); }

__device__ __forceinline__ void ldsm4(uint32_t* r, uint32_t addr) {
    asm volatile("ldmatrix.sync.aligned.m8n8.x4.shared.b16 {%0,%1,%2,%3}, [%4];"
                 : "=r"(r[0]), "=r"(r[1]), "=r"(r[2]), "=r"(r[3]) : "r"(addr));
}
__device__ __forceinline__ void hmma(float* c, const uint32_t* a, const uint32_t* b) {
    asm volatile(
        "mma.sync.aligned.m16n8k16.row.col.f32.bf16.bf16.f32 "
        "{%0,%1,%2,%3}, {%4,%5,%6,%7}, {%8,%9}, {%0,%1,%2,%3};"
        : "+f"(c[0]), "+f"(c[1]), "+f"(c[2]), "+f"(c[3])
        : "r"(a[0]), "r"(a[1]), "r"(a[2]), "r"(a[3]), "r"(b[0]), "r"(b[1]));
}

// ---------------------------------------------------------------------------
// K1: normalize (fp32 division, like jax) + bf16 hi cast
// ---------------------------------------------------------------------------
__global__ void normalize_kernel(const float* __restrict__ F1,
                                 const float* __restrict__ F2) {
    int gw = (blockIdx.x * blockDim.x + threadIdx.x) >> 5;
    int lane = threadIdx.x & 31;
    const int R = B_ * N_;
    if (gw >= 2 * R) return;

    const float* src;
    __nv_bfloat16* dst;
    float* fdst;
    int row;
    if (gw < R) { src = F1; dst = g_a; fdst = g_f1n; row = gw; }
    else        { src = F2; dst = g_b; fdst = g_f2n; row = gw - R; }

    const float4* s4 = (const float4*)(src + (size_t)row * D_);
    float4 v0 = s4[lane];
    float4 v1 = s4[lane + 32];
    float ss = v0.x*v0.x + v0.y*v0.y + v0.z*v0.z + v0.w*v0.w
             + v1.x*v1.x + v1.y*v1.y + v1.z*v1.z + v1.w*v1.w;
#pragma unroll
    for (int o = 16; o; o >>= 1) ss += __shfl_xor_sync(0xffffffffu, ss, o);
    float nrm = fmaxf(sqrtf(ss), 1e-12f);

    float f[8] = {v0.x/nrm, v0.y/nrm, v0.z/nrm, v0.w/nrm,
                  v1.x/nrm, v1.y/nrm, v1.z/nrm, v1.w/nrm};

    float4* o4 = (float4*)(fdst + (size_t)row * D_);
    o4[lane]      = make_float4(f[0], f[1], f[2], f[3]);
    o4[lane + 32] = make_float4(f[4], f[5], f[6], f[7]);

    __nv_bfloat16* rp = dst + (size_t)row * D_;
#pragma unroll
    for (int i = 0; i < 8; i++) {
        int c = (i < 4) ? (lane * 4 + i) : (128 + lane * 4 + i - 4);
        rp[c] = __float2bfloat16_rn(f[i]);
    }
}

// ---------------------------------------------------------------------------
// K2: pure bf16 HMMA GEMM, sim -> out[0 .. B*N*N)
// CTA tile 64(m) x 128(n), K=256 in 4 stages of 64; 256 thr (8 warps 2m x 4n)
// ---------------------------------------------------------------------------
#define GM_AB 8192                  // 64 rows * 128B
#define GM_BB 16384                 // 128 rows * 128B
#define GM_SB (GM_AB + GM_BB)       // 24576
#define GM_SMEM (3 * GM_SB)         // 73728

__device__ __forceinline__ void gemm_issue(uint32_t sbase, int s,
                                           const char* gA, const char* gB, int tid) {
    const uint32_t base = sbase + (s % 3) * GM_SB;
    const int kb = s * 128;
#pragma unroll
    for (int i = 0; i < 2; i++) {          // A: 512 chunks
        int ch = i * 256 + tid;
        int r = ch >> 3, c = ch & 7;
        cp16(base + swz(r * 128 + c * 16), gA + (size_t)r * 512 + kb + c * 16);
    }
#pragma unroll
    for (int i = 0; i < 4; i++) {          // B: 1024 chunks
        int ch = i * 256 + tid;
        int r = ch >> 3, c = ch & 7;
        cp16(base + GM_AB + swz(r * 128 + c * 16), gB + (size_t)r * 512 + kb + c * 16);
    }
    CP_COMMIT();
}

__global__ __launch_bounds__(256, 2) void gemm_sim(float* __restrict__ out) {
    extern __shared__ char smem[];
    const uint32_t sbase = smem_u32(smem);

    const int tid  = threadIdx.x;
    const int wid  = tid >> 5;
    const int lane = tid & 31;
    const int wm   = wid & 1;        // 2 row groups of 32
    const int wn   = wid >> 1;       // 4 col groups of 32
    const int bb   = blockIdx.z;
    const int m0   = blockIdx.y * 64;
    const int n0   = blockIdx.x * 128;

    const char* gA = (const char*)g_a + ((size_t)(bb * N_ + m0)) * 512;
    const char* gB = (const char*)g_b + ((size_t)(bb * N_ + n0)) * 512;

    const int g  = lane >> 3;
    const int lr = lane & 7;
    const uint32_t aoff = (uint32_t)((wm * 32 + (g & 1) * 8 + lr) * 128 + (g >> 1) * 16);
    const uint32_t boff = (uint32_t)((wn * 32 + (g >> 1) * 8 + lr) * 128 + (g & 1) * 16);

    float C[2][4][4];
#pragma unroll
    for (int mt = 0; mt < 2; mt++)
#pragma unroll
        for (int nt = 0; nt < 4; nt++)
#pragma unroll
            for (int e = 0; e < 4; e++) C[mt][nt][e] = 0.0f;

    gemm_issue(sbase, 0, gA, gB, tid);
    gemm_issue(sbase, 1, gA, gB, tid);

    for (int s = 0; s < 4; ++s) {
        CP_WAIT1();
        __syncthreads();
        if (s + 2 < 4) gemm_issue(sbase, s + 2, gA, gB, tid);
        else CP_COMMIT();

        const uint32_t sA = sbase + (s % 3) * GM_SB;
        const uint32_t sB = sA + GM_AB;
#pragma unroll
        for (int kk = 0; kk < 4; kk++) {
            uint32_t a0[4], a1[4], b[2][4];
            ldsm4(a0, sA + swz(aoff + kk * 32));
            ldsm4(a1, sA + swz(aoff + 2048 + kk * 32));
#pragma unroll
            for (int p = 0; p < 2; p++)
                ldsm4(b[p], sB + swz(boff + p * 2048 + kk * 32));
#pragma unroll
            for (int p = 0; p < 2; p++) {
                hmma(C[0][2 * p + 0], a0, &b[p][0]);
                hmma(C[0][2 * p + 1], a0, &b[p][2]);
                hmma(C[1][2 * p + 0], a1, &b[p][0]);
                hmma(C[1][2 * p + 1], a1, &b[p][2]);
            }
        }
    }

    // direct store to gmem
#pragma unroll
    for (int mt = 0; mt < 2; mt++) {
        const int r = m0 + wm * 32 + mt * 16 + (lane >> 2);
        float* rp0 = out + ((size_t)bb * N_ + r) * N_ + n0;
        float* rp1 = rp0 + 8 * N_;
#pragma unroll
        for (int nt = 0; nt < 4; nt++) {
            const int c = wn * 32 + nt * 8 + 2 * (lane & 3);
            *(float2*)(rp0 + c) = make_float2(C[mt][nt][0], C[mt][nt][1]);
            *(float2*)(rp1 + c) = make_float2(C[mt][nt][2], C[mt][nt][3]);
        }
    }
}

// ---------------------------------------------------------------------------
// K3: candidate select — 2 threads per row, exact top-40 per row
// block 128 (64 rows), grid 256
// ---------------------------------------------------------------------------
__device__ __forceinline__ void insert_cand_s(float* tv, int* ti, float v, int idx) {
    int pos = NC - 1;
    while (pos > 0 && tv[pos - 1] < v) {
        tv[pos] = tv[pos - 1];
        ti[pos] = ti[pos - 1];
        pos--;
    }
    tv[pos] = v;
    ti[pos] = idx;
}

__global__ __launch_bounds__(128) void select_cand(const float* __restrict__ sim) {
    __shared__ float sv[128][NC];
    __shared__ int   si[128][NC];

    const int tid  = threadIdx.x;
    const int grow = blockIdx.x * 64 + (tid >> 1);
    const int half = tid & 1;

    float* tv = sv[tid];
    int*   ti = si[tid];
#pragma unroll
    for (int k = 0; k < NC; k++) { tv[k] = -3.4e38f; ti[k] = 0; }

    const float4* p = (const float4*)(sim + (size_t)grow * N_ + half * 2048);
    float tmin = -3.4e38f;

    for (int it = 0; it < 128; ++it) {          // 128 x 16 floats = 2048
        float4 x0 = p[it * 4 + 0];
        float4 x1 = p[it * 4 + 1];
        float4 x2 = p[it * 4 + 2];
        float4 x3 = p[it * 4 + 3];
        float m01 = fmaxf(fmaxf(x0.x, x0.y), fmaxf(x0.z, x0.w));
        float m23 = fmaxf(fmaxf(x1.x, x1.y), fmaxf(x1.z, x1.w));
        float m45 = fmaxf(fmaxf(x2.x, x2.y), fmaxf(x2.z, x2.w));
        float m67 = fmaxf(fmaxf(x3.x, x3.y), fmaxf(x3.z, x3.w));
        float mx = fmaxf(fmaxf(m01, m23), fmaxf(m45, m67));
        if (mx > tmin) {
            const int cb = half * 2048 + it * 16;
            float vals[16] = {x0.x, x0.y, x0.z, x0.w, x1.x, x1.y, x1.z, x1.w,
                              x2.x, x2.y, x2.z, x2.w, x3.x, x3.y, x3.z, x3.w};
#pragma unroll
            for (int j = 0; j < 16; j++) {
                if (vals[j] > tmin) {
                    insert_cand_s(tv, ti, vals[j], cb + j);
                    tmin = tv[NC - 1];
                }
            }
        }
    }
    __syncthreads();

    if (half == 0) {    // merge halves (half0 first on ties -> lower idx wins)
        const float* v0 = sv[tid];
        const int*   i0 = si[tid];
        const float* v1 = sv[tid + 1];
        const int*   i1 = si[tid + 1];
        float* ov = g_cv + (size_t)grow * NC;
        int*   oi = g_ci + (size_t)grow * NC;
        int a = 0, b2 = 0;
#pragma unroll
        for (int k = 0; k < NC; k++) {
            if (v0[a] >= v1[b2]) { ov[k] = v0[a]; oi[k] = i0[a]; a++; }
            else                 { ov[k] = v1[b2]; oi[k] = i1[b2]; b2++; }
        }
    }
}

// ---------------------------------------------------------------------------
// K4: finalize — warp per row: exact fp32 rescore, stable top-32, softmax,
// zero the sim row, scatter weights + indices
// ---------------------------------------------------------------------------
__device__ __forceinline__ void insert_final(float* tv, int* ti, float v, int idx) {
    int pos = K_ - 1;
    while (pos > 0 && (tv[pos - 1] < v || (tv[pos - 1] == v && ti[pos - 1] > idx))) {
        tv[pos] = tv[pos - 1];
        ti[pos] = ti[pos - 1];
        pos--;
    }
    tv[pos] = v;
    ti[pos] = idx;
}

__global__ __launch_bounds__(256) void finalize(float* __restrict__ out) {
    __shared__ float sw[8][K_];
    __shared__ int   sidx[8][K_];

    const int wid  = threadIdx.x >> 5;
    const int lane = threadIdx.x & 31;
    const int grow = blockIdx.x * 8 + wid;
    const int bb   = grow >> 12;

    const float4* a4 = (const float4*)(g_f1n + (size_t)grow * D_);
    float4 a0 = a4[lane], a1 = a4[lane + 32];

    int myc0 = g_ci[(size_t)grow * NC + lane];
    int myc1 = (lane < NC - 32) ? g_ci[(size_t)grow * NC + 32 + lane] : 0;

    float tv[K_];
    int ti[K_];
#pragma unroll
    for (int k = 0; k < K_; k++) { tv[k] = -3.4e38f; ti[k] = 0x7fffffff; }

    const float* f2b = g_f2n + ((size_t)bb << 12) * D_;
#pragma unroll 2
    for (int c = 0; c < NC; ++c) {
        int col = (c < 32) ? __shfl_sync(0xffffffffu, myc0, c)
                           : __shfl_sync(0xffffffffu, myc1, c - 32);
        const float4* b4 = (const float4*)(f2b + (size_t)col * D_);
        float4 b0 = b4[lane], b1 = b4[lane + 32];
        float s = a0.x * b0.x;
        s = fmaf(a0.y, b0.y, s);
        s = fmaf(a0.z, b0.z, s);
        s = fmaf(a0.w, b0.w, s);
        s = fmaf(a1.x, b1.x, s);
        s = fmaf(a1.y, b1.y, s);
        s = fmaf(a1.z, b1.z, s);
        s = fmaf(a1.w, b1.w, s);
#pragma unroll
        for (int o = 16; o; o >>= 1) s += __shfl_xor_sync(0xffffffffu, s, o);
        if (lane == 0) {
            if (s > tv[K_ - 1] || (s == tv[K_ - 1] && col < ti[K_ - 1]))
                insert_final(tv, ti, s, col);
        }
    }

    if (lane == 0) {
        float mx = tv[0];
        float e[K_];
        float sum = 0.0f;
#pragma unroll
        for (int k = 0; k < K_; k++) { e[k] = expf((tv[k] - mx) * INV_T); sum += e[k]; }
        float inv = 1.0f / sum;
#pragma unroll
        for (int k = 0; k < K_; k++) { sw[wid][k] = e[k] * inv; sidx[wid][k] = ti[k]; }
    }
    __syncwarp();

    // zero the sim row
    float4* rowp = (float4*)(out + (size_t)grow * N_);
    const float4 z = make_float4(0.f, 0.f, 0.f, 0.f);
#pragma unroll
    for (int i = 0; i < 32; i++) rowp[i * 32 + lane] = z;
    __syncwarp();

    // scatter
    out[(size_t)grow * N_ + sidx[wid][lane]] = sw[wid][lane];
    out[(size_t)B_ * N_ * N_ + (size_t)grow * K_ + lane] = (float)sidx[wid][lane];
}

// ---------------------------------------------------------------------------
extern "C" void kernel_launch(void* const* d_in, const int* in_sizes, int n_in,
                              void* d_out, int out_size) {
    const float* F1 = (const float*)d_in[0];
    const float* F2 = (const float*)d_in[1];
    float* out = (float*)d_out;

    normalize_kernel<<<4096, 256>>>(F1, F2);

    cudaFuncSetAttribute(gemm_sim,
                         cudaFuncAttributeMaxDynamicSharedMemorySize, GM_SMEM);
    gemm_sim<<<dim3(N_ / 128, N_ / 64, B_), 256, GM_SMEM>>>(out);

    select_cand<<<(B_ * N_) / 64, 128>>>(out);

    finalize<<<(B_ * N_) / 8, 256>>>(out);
}